// round 2
// baseline (speedup 1.0000x reference)
#include <cuda_runtime.h>
#include <cuda_bf16.h>
#include <math.h>

#define N_TOK 2048
#define HDIM 1024
#define FDIM 4096
#define NEXP 8
#define KSEL 2
#define NPAIR (N_TOK*KSEL)
#define MAXTILES 40

// ---------------- scratch (static device globals; no runtime allocation) ----------------
__device__ float g_logits[N_TOK*NEXP];
__device__ float g_soft[N_TOK*NEXP];
__device__ float g_wn[NPAIR];
__device__ int   g_slot[NPAIR];
__device__ int   g_pairtok[NPAIR];
__device__ int   g_tiles[MAXTILES*3];
__device__ int   g_ntiles;
__device__ float g_H[(size_t)(NPAIR+128)*FDIM];   // gelu(x@W1+b1) per pair slot (padded rows)
__device__ float g_Y[(size_t)(NPAIR+128)*HDIM];   // (h@W2+b2) per pair slot

// ---------------- helpers ----------------
__device__ __forceinline__ unsigned f2tf32(float x){
    unsigned r;
    asm("cvt.rna.tf32.f32 %0, %1;" : "=r"(r) : "f"(x));
    return r;
}

__device__ __forceinline__ void mma_tf32(float c[4], unsigned a0, unsigned a1, unsigned a2, unsigned a3,
                                         unsigned b0, unsigned b1){
    asm volatile("mma.sync.aligned.m16n8k8.row.col.f32.tf32.tf32.f32 "
        "{%0,%1,%2,%3}, {%4,%5,%6,%7}, {%8,%9}, {%0,%1,%2,%3};\n"
        : "+f"(c[0]),"+f"(c[1]),"+f"(c[2]),"+f"(c[3])
        : "r"(a0),"r"(a1),"r"(a2),"r"(a3),"r"(b0),"r"(b1));
}

__device__ __forceinline__ float gelu_t(float v){
    float u = 0.7978845608028654f*(v + 0.044715f*v*v*v);
    return 0.5f*v*(1.f + tanhf(u));
}

// ---------------- 1) gating logits: x @ Wg^T  (fp32 exact) ----------------
__global__ void gate_kernel(const float* __restrict__ x, const float* __restrict__ Wg,
                            float* __restrict__ logits){
    int i = blockIdx.x;
    int wid = threadIdx.x >> 5;
    int lane = threadIdx.x & 31;
    const float4* x4 = reinterpret_cast<const float4*>(x + (size_t)i*HDIM);
    const float4* w4 = reinterpret_cast<const float4*>(Wg + (size_t)wid*HDIM);
    float s = 0.f;
    #pragma unroll
    for (int k = lane; k < HDIM/4; k += 32){
        float4 a = x4[k], b = w4[k];
        s += a.x*b.x + a.y*b.y + a.z*b.z + a.w*b.w;
    }
    #pragma unroll
    for (int o = 16; o; o >>= 1) s += __shfl_xor_sync(0xffffffffu, s, o);
    if (lane == 0) logits[i*NEXP + wid] = s;
}

// ---------------- 2) softmax over axis=0 (per expert column) ----------------
__global__ void colsoftmax_kernel(const float* __restrict__ logits, float* __restrict__ soft){
    int e = blockIdx.x;
    int t = threadIdx.x;
    __shared__ float red[256];
    float m = -1e30f;
    for (int i = t; i < N_TOK; i += 256) m = fmaxf(m, logits[i*NEXP + e]);
    red[t] = m; __syncthreads();
    for (int o = 128; o; o >>= 1){ if (t < o) red[t] = fmaxf(red[t], red[t+o]); __syncthreads(); }
    float mx = red[0]; __syncthreads();
    float sum = 0.f;
    for (int i = t; i < N_TOK; i += 256) sum += expf(logits[i*NEXP + e] - mx);
    red[t] = sum; __syncthreads();
    for (int o = 128; o; o >>= 1){ if (t < o) red[t] += red[t+o]; __syncthreads(); }
    float inv = 1.f / red[0];
    for (int i = t; i < N_TOK; i += 256)
        soft[i*NEXP + e] = expf(logits[i*NEXP + e] - mx) * inv;
}

// ---------------- 3) deterministic assignment ----------------
__global__ void assign_kernel(const int* __restrict__ mapping, const float* __restrict__ soft){
    const int T = 512, PPT = NPAIR / T;
    int t = threadIdx.x;
    __shared__ int scan[T][NEXP];
    __shared__ int base[NEXP];

    int cnt[NEXP];
    #pragma unroll
    for (int e = 0; e < NEXP; e++) cnt[e] = 0;
    int le[PPT], lr[PPT];
    #pragma unroll
    for (int j = 0; j < PPT; j++){
        int p = t*PPT + j;
        int e = mapping[p];
        le[j] = e; lr[j] = cnt[e]; cnt[e]++;
    }
    #pragma unroll
    for (int e = 0; e < NEXP; e++) scan[t][e] = cnt[e];
    __syncthreads();
    for (int off = 1; off < T; off <<= 1){
        int v[NEXP];
        if (t >= off){
            #pragma unroll
            for (int e = 0; e < NEXP; e++) v[e] = scan[t-off][e];
        }
        __syncthreads();
        if (t >= off){
            #pragma unroll
            for (int e = 0; e < NEXP; e++) scan[t][e] += v[e];
        }
        __syncthreads();
    }
    if (t == 0){
        int acc = 0;
        for (int e = 0; e < NEXP; e++){ base[e] = acc; acc += scan[T-1][e]; }
        int nt = 0;
        for (int e = 0; e < NEXP; e++){
            int c = scan[T-1][e];
            for (int r = 0; r < c; r += 128){
                g_tiles[nt*3+0] = e;
                g_tiles[nt*3+1] = base[e] + r;
                g_tiles[nt*3+2] = min(128, c - r);
                nt++;
            }
        }
        g_ntiles = nt;
    }
    __syncthreads();
    int excl[NEXP];
    #pragma unroll
    for (int e = 0; e < NEXP; e++) excl[e] = (t > 0 ? scan[t-1][e] : 0);
    #pragma unroll
    for (int j = 0; j < PPT; j++){
        int p = t*PPT + j;
        int e = le[j];
        int dst = base[e] + excl[e] + lr[j];
        g_slot[p] = dst;
        g_pairtok[dst] = p >> 1;
    }
    #pragma unroll
    for (int ii = 0; ii < PPT/KSEL; ii++){
        int i = t*(PPT/KSEL) + ii;
        int e0 = mapping[i*KSEL], e1 = mapping[i*KSEL+1];
        float w0 = soft[i*NEXP + e0], w1 = soft[i*NEXP + e1];
        float inv = 1.f / (w0 + w1);
        g_wn[i*KSEL]   = w0*inv;
        g_wn[i*KSEL+1] = w1*inv;
    }
}

// ---------------- 4) tf32 grouped GEMM: 128x128 tile, BK=16, 4 warps, 64x64 warp tile ----------------
template<int KSIZE, int LDB, bool GELU, bool GATHER>
__global__ __launch_bounds__(128) void moe_gemm_kernel(
    const float* __restrict__ Asrc,
    const float* __restrict__ Ball,   // W [E][KSIZE][LDB]
    const float* __restrict__ bias,   // [E][LDB]
    float* __restrict__ Cbuf,         // ld = LDB
    const int* __restrict__ pairtok)
{
    int tileIdx = blockIdx.x;
    if (tileIdx >= g_ntiles) return;
    int e    = g_tiles[tileIdx*3+0];
    int row0 = g_tiles[tileIdx*3+1];
    int rows = g_tiles[tileIdx*3+2];
    int n0   = blockIdx.y * 128;

    extern __shared__ float smem[];
    const int ASTR = 20, BSTR = 136;      // BK=16 (+4 pad), 128 (+8 pad): conflict-free
    const int ASZ = 128*ASTR, BSZ = 16*BSTR;
    float* As = smem;                     // [2][128][20]
    float* Bs = smem + 2*ASZ;             // [2][16][136]

    int tid = threadIdx.x;
    int wid = tid >> 5, lane = tid & 31;
    int wm = (wid >> 1) * 64, wn = (wid & 1) * 64;

    // A staging: one row per thread, 16 floats (4x float4)
    const float* aptr;
    if (GATHER){
        int rr = row0 + ((tid < rows) ? tid : (rows - 1));
        int tok = pairtok[rr];
        aptr = Asrc + (size_t)tok * KSIZE;
    } else {
        aptr = Asrc + (size_t)(row0 + tid) * KSIZE;
    }
    // B staging: rb = tid>>3 (16 rows), 4x float4 with stride 32
    int rb   = tid >> 3;
    int bcol = (tid & 7) * 4;
    const float* bptr = Ball + (size_t)e * KSIZE * LDB + (size_t)rb * LDB + n0 + bcol;

    float c[4][8][4];
    #pragma unroll
    for (int i = 0; i < 4; i++)
        #pragma unroll
        for (int j = 0; j < 8; j++)
            #pragma unroll
            for (int q = 0; q < 4; q++) c[i][j][q] = 0.f;

    float4 ar[4], br[4];
    #pragma unroll
    for (int j = 0; j < 4; j++) ar[j] = *reinterpret_cast<const float4*>(aptr + j*4);
    #pragma unroll
    for (int j = 0; j < 4; j++) br[j] = *reinterpret_cast<const float4*>(bptr + j*32);

    auto sts_tiles = [&](int buf){
        float* da = As + buf*ASZ + tid*ASTR;
        #pragma unroll
        for (int j = 0; j < 4; j++){
            float4 v = ar[j];
            v.x = __uint_as_float(f2tf32(v.x)); v.y = __uint_as_float(f2tf32(v.y));
            v.z = __uint_as_float(f2tf32(v.z)); v.w = __uint_as_float(f2tf32(v.w));
            *reinterpret_cast<float4*>(da + j*4) = v;
        }
        float* db = Bs + buf*BSZ + rb*BSTR + bcol;
        #pragma unroll
        for (int j = 0; j < 4; j++){
            float4 v = br[j];
            v.x = __uint_as_float(f2tf32(v.x)); v.y = __uint_as_float(f2tf32(v.y));
            v.z = __uint_as_float(f2tf32(v.z)); v.w = __uint_as_float(f2tf32(v.w));
            *reinterpret_cast<float4*>(db + j*32) = v;
        }
    };
    sts_tiles(0);
    __syncthreads();

    const int NKT = KSIZE / 16;
    for (int kt = 0; kt < NKT; kt++){
        int cur = kt & 1;
        if (kt + 1 < NKT){
            const float* ap = aptr + (kt+1)*16;
            #pragma unroll
            for (int j = 0; j < 4; j++) ar[j] = *reinterpret_cast<const float4*>(ap + j*4);
            const float* bp = bptr + (size_t)(kt+1)*16*LDB;
            #pragma unroll
            for (int j = 0; j < 4; j++) br[j] = *reinterpret_cast<const float4*>(bp + j*32);
        }
        const float* Ab = As + cur*ASZ;
        const float* Bb = Bs + cur*BSZ;
        #pragma unroll
        for (int ks = 0; ks < 2; ks++){
            int k0 = ks*8;
            unsigned afr[4][4], bfr[8][2];
            #pragma unroll
            for (int fm = 0; fm < 4; fm++){
                const float* p = Ab + (wm + fm*16 + (lane>>2))*ASTR + k0 + (lane&3);
                afr[fm][0] = __float_as_uint(p[0]);
                afr[fm][1] = __float_as_uint(p[8*ASTR]);
                afr[fm][2] = __float_as_uint(p[4]);
                afr[fm][3] = __float_as_uint(p[8*ASTR + 4]);
            }
            #pragma unroll
            for (int fn = 0; fn < 8; fn++){
                const float* p = Bb + (k0 + (lane&3))*BSTR + wn + fn*8 + (lane>>2);
                bfr[fn][0] = __float_as_uint(p[0]);
                bfr[fn][1] = __float_as_uint(p[4*BSTR]);
            }
            #pragma unroll
            for (int fm = 0; fm < 4; fm++)
                #pragma unroll
                for (int fn = 0; fn < 8; fn++)
                    mma_tf32(c[fm][fn], afr[fm][0], afr[fm][1], afr[fm][2], afr[fm][3],
                             bfr[fn][0], bfr[fn][1]);
        }
        if (kt + 1 < NKT) sts_tiles(cur ^ 1);
        __syncthreads();
    }

    // epilogue
    int r_lane = lane >> 2, c_lane = (lane & 3) * 2;
    #pragma unroll
    for (int fm = 0; fm < 4; fm++){
        #pragma unroll
        for (int half = 0; half < 2; half++){
            int mloc = wm + fm*16 + half*8 + r_lane;
            if (mloc < rows){
                float* outp = Cbuf + (size_t)(row0 + mloc)*LDB + n0;
                const float* bp2 = bias + (size_t)e*LDB + n0;
                #pragma unroll
                for (int fn = 0; fn < 8; fn++){
                    int col = wn + fn*8 + c_lane;
                    float v0 = c[fm][fn][half*2+0] + bp2[col];
                    float v1 = c[fm][fn][half*2+1] + bp2[col+1];
                    if (GELU){ v0 = gelu_t(v0); v1 = gelu_t(v1); }
                    float2 st; st.x = v0; st.y = v1;
                    *reinterpret_cast<float2*>(outp + col) = st;
                }
            }
        }
    }
}

// ---------------- 5) weighted combine ----------------
__global__ void combine_kernel(float* __restrict__ out){
    int i = blockIdx.x, t = threadIdx.x;
    int s0 = g_slot[i*2], s1 = g_slot[i*2+1];
    float w0 = g_wn[i*2], w1 = g_wn[i*2+1];
    const float4* y0 = reinterpret_cast<const float4*>(g_Y + (size_t)s0*HDIM);
    const float4* y1 = reinterpret_cast<const float4*>(g_Y + (size_t)s1*HDIM);
    float4 a = y0[t], b = y1[t];
    float4 r;
    r.x = w0*a.x + w1*b.x; r.y = w0*a.y + w1*b.y;
    r.z = w0*a.z + w1*b.z; r.w = w0*a.w + w1*b.w;
    reinterpret_cast<float4*>(out + (size_t)i*HDIM)[t] = r;
}

// ---------------- launch ----------------
extern "C" void kernel_launch(void* const* d_in, const int* in_sizes, int n_in,
                              void* d_out, int out_size){
    const float* x       = (const float*)d_in[0];
    const int*   mapping = (const int*)  d_in[1];
    const float* Wg      = (const float*)d_in[2];
    const float* W1      = (const float*)d_in[3];
    const float* b1      = (const float*)d_in[4];
    const float* W2      = (const float*)d_in[5];
    const float* b2      = (const float*)d_in[6];
    float* out = (float*)d_out;

    float *pLog, *pSoft, *pH, *pY; int *pTok;
    cudaGetSymbolAddress((void**)&pLog,  g_logits);
    cudaGetSymbolAddress((void**)&pSoft, g_soft);
    cudaGetSymbolAddress((void**)&pH,    g_H);
    cudaGetSymbolAddress((void**)&pY,    g_Y);
    cudaGetSymbolAddress((void**)&pTok,  g_pairtok);

    gate_kernel<<<N_TOK, 256>>>(x, Wg, pLog);
    colsoftmax_kernel<<<NEXP, 256>>>(pLog, pSoft);
    assign_kernel<<<1, 512>>>(mapping, pSoft);

    int smem = (2*128*20 + 2*16*136) * (int)sizeof(float);  // 37888 B
    cudaFuncSetAttribute(moe_gemm_kernel<HDIM, FDIM, true,  true >,
                         cudaFuncAttributeMaxDynamicSharedMemorySize, smem);
    cudaFuncSetAttribute(moe_gemm_kernel<FDIM, HDIM, false, false>,
                         cudaFuncAttributeMaxDynamicSharedMemorySize, smem);

    moe_gemm_kernel<HDIM, FDIM, true,  true ><<<dim3(MAXTILES, FDIM/128), 128, smem>>>(x,  W1, b1, pH, pTok);
    moe_gemm_kernel<FDIM, HDIM, false, false><<<dim3(MAXTILES, HDIM/128), 128, smem>>>(pH, W2, b2, pY, pTok);

    combine_kernel<<<N_TOK, 256>>>(out);
}

// round 4
// speedup vs baseline: 1.4602x; 1.4602x over previous
#include <cuda_runtime.h>
#include <cuda_fp16.h>
#include <math.h>
#include <cstdint>

#define N_TOK 2048
#define HDIM 1024
#define FDIM 4096
#define NEXP 8
#define KSEL 2
#define NPAIR (N_TOK*KSEL)
#define MAXTILES 40
#define BK 32

// ---------------- scratch (static device globals) ----------------
__device__ float  g_logits[N_TOK*NEXP];
__device__ float  g_soft[N_TOK*NEXP];
__device__ float  g_wn[NPAIR];
__device__ int    g_slot[NPAIR];
__device__ int    g_pairtok[NPAIR];
__device__ int    g_tiles[MAXTILES*3];
__device__ int    g_ntiles;
__device__ __half g_Hh[(size_t)(NPAIR+128)*FDIM];   // gelu(x@W1+b1) as fp16
__device__ float  g_Y[(size_t)(NPAIR+128)*HDIM];

// ---------------- helpers ----------------
__device__ __forceinline__ uint32_t pack_h2(float lo, float hi){
    uint32_t r;
    asm("cvt.rn.f16x2.f32 %0, %1, %2;" : "=r"(r) : "f"(hi), "f"(lo));
    return r;
}

__device__ __forceinline__ void mma_fp16(float c[4], uint32_t a0, uint32_t a1, uint32_t a2, uint32_t a3,
                                         uint32_t b0, uint32_t b1){
    asm volatile("mma.sync.aligned.m16n8k16.row.col.f32.f16.f16.f32 "
        "{%0,%1,%2,%3}, {%4,%5,%6,%7}, {%8,%9}, {%0,%1,%2,%3};\n"
        : "+f"(c[0]),"+f"(c[1]),"+f"(c[2]),"+f"(c[3])
        : "r"(a0),"r"(a1),"r"(a2),"r"(a3),"r"(b0),"r"(b1));
}

__device__ __forceinline__ float gelu_t(float v){
    float u = 0.7978845608028654f*(v + 0.044715f*v*v*v);
    return 0.5f*v*(1.f + tanhf(u));
}

// ---------------- 1) gating logits: x @ Wg^T ----------------
__global__ void gate_kernel(const float* __restrict__ x, const float* __restrict__ Wg,
                            float* __restrict__ logits){
    int i = blockIdx.x;
    int wid = threadIdx.x >> 5;
    int lane = threadIdx.x & 31;
    const float4* x4 = reinterpret_cast<const float4*>(x + (size_t)i*HDIM);
    const float4* w4 = reinterpret_cast<const float4*>(Wg + (size_t)wid*HDIM);
    float s = 0.f;
    #pragma unroll
    for (int k = lane; k < HDIM/4; k += 32){
        float4 a = x4[k], b = w4[k];
        s += a.x*b.x + a.y*b.y + a.z*b.z + a.w*b.w;
    }
    #pragma unroll
    for (int o = 16; o; o >>= 1) s += __shfl_xor_sync(0xffffffffu, s, o);
    if (lane == 0) logits[i*NEXP + wid] = s;
}

// ---------------- 2) softmax over axis=0 ----------------
__global__ void colsoftmax_kernel(const float* __restrict__ logits, float* __restrict__ soft){
    int e = blockIdx.x;
    int t = threadIdx.x;
    __shared__ float red[256];
    float m = -1e30f;
    for (int i = t; i < N_TOK; i += 256) m = fmaxf(m, logits[i*NEXP + e]);
    red[t] = m; __syncthreads();
    for (int o = 128; o; o >>= 1){ if (t < o) red[t] = fmaxf(red[t], red[t+o]); __syncthreads(); }
    float mx = red[0]; __syncthreads();
    float sum = 0.f;
    for (int i = t; i < N_TOK; i += 256) sum += expf(logits[i*NEXP + e] - mx);
    red[t] = sum; __syncthreads();
    for (int o = 128; o; o >>= 1){ if (t < o) red[t] += red[t+o]; __syncthreads(); }
    float inv = 1.f / red[0];
    for (int i = t; i < N_TOK; i += 256)
        soft[i*NEXP + e] = expf(logits[i*NEXP + e] - mx) * inv;
}

// ---------------- 3) deterministic assignment ----------------
__global__ void assign_kernel(const int* __restrict__ mapping, const float* __restrict__ soft){
    const int T = 512, PPT = NPAIR / T;
    int t = threadIdx.x;
    __shared__ int scan[T][NEXP];
    __shared__ int base[NEXP];

    int cnt[NEXP];
    #pragma unroll
    for (int e = 0; e < NEXP; e++) cnt[e] = 0;
    int le[PPT], lr[PPT];
    #pragma unroll
    for (int j = 0; j < PPT; j++){
        int p = t*PPT + j;
        int e = mapping[p];
        le[j] = e; lr[j] = cnt[e]; cnt[e]++;
    }
    #pragma unroll
    for (int e = 0; e < NEXP; e++) scan[t][e] = cnt[e];
    __syncthreads();
    for (int off = 1; off < T; off <<= 1){
        int v[NEXP];
        if (t >= off){
            #pragma unroll
            for (int e = 0; e < NEXP; e++) v[e] = scan[t-off][e];
        }
        __syncthreads();
        if (t >= off){
            #pragma unroll
            for (int e = 0; e < NEXP; e++) scan[t][e] += v[e];
        }
        __syncthreads();
    }
    if (t == 0){
        int acc = 0;
        for (int e = 0; e < NEXP; e++){ base[e] = acc; acc += scan[T-1][e]; }
        int nt = 0;
        for (int e = 0; e < NEXP; e++){
            int c = scan[T-1][e];
            for (int r = 0; r < c; r += 128){
                g_tiles[nt*3+0] = e;
                g_tiles[nt*3+1] = base[e] + r;
                g_tiles[nt*3+2] = min(128, c - r);
                nt++;
            }
        }
        g_ntiles = nt;
    }
    __syncthreads();
    int excl[NEXP];
    #pragma unroll
    for (int e = 0; e < NEXP; e++) excl[e] = (t > 0 ? scan[t-1][e] : 0);
    #pragma unroll
    for (int j = 0; j < PPT; j++){
        int p = t*PPT + j;
        int e = le[j];
        int dst = base[e] + excl[e] + lr[j];
        g_slot[p] = dst;
        g_pairtok[dst] = p >> 1;
    }
    #pragma unroll
    for (int ii = 0; ii < PPT/KSEL; ii++){
        int i = t*(PPT/KSEL) + ii;
        int e0 = mapping[i*KSEL], e1 = mapping[i*KSEL+1];
        float w0 = soft[i*NEXP + e0], w1 = soft[i*NEXP + e1];
        float inv = 1.f / (w0 + w1);
        g_wn[i*KSEL]   = w0*inv;
        g_wn[i*KSEL+1] = w1*inv;
    }
}

// ---------------- 4) fp16 grouped GEMM: 128x128 tile, BK=32, 8 warps, 64x32 warp tile ----------------
// A smem: [2][128][40] half (K-contig). B smem: [2][128][40] half (N-major: [n][k]).
template<int KSIZE, int LDB, bool GELU, bool GATHER>
__global__ __launch_bounds__(256, 2) void moe_gemm_fp16(
    const void* __restrict__ Asrc,    // float x (GATHER) or half g_Hh
    const float* __restrict__ Ball,   // W [E][KSIZE][LDB] fp32
    const float* __restrict__ bias,   // [E][LDB]
    void* __restrict__ Cbuf,          // half (GELU) or float
    const int* __restrict__ pairtok)
{
    int tileIdx = blockIdx.x;
    if (tileIdx >= g_ntiles) return;
    int e    = g_tiles[tileIdx*3+0];
    int row0 = g_tiles[tileIdx*3+1];
    int rows = g_tiles[tileIdx*3+2];
    int n0   = blockIdx.y * 128;

    extern __shared__ __half smem[];
    const int ASTR = 40, BSTR = 40;
    const int ASZ = 128*ASTR, BSZ = 128*BSTR;
    __half* As = smem;
    __half* Bs = smem + 2*ASZ;

    int tid = threadIdx.x;
    int wid = tid >> 5, lane = tid & 31;
    int wm = (wid >> 2) * 64, wn = (wid & 3) * 32;

    // ---- A staging: thread -> row tid>>1, half-offset (tid&1)*16 ----
    int arow = tid >> 1;
    int koff = (tid & 1) * 16;
    const float*  aF = nullptr;
    const __half* aH = nullptr;
    if (GATHER){
        int rr = row0 + ((arow < rows) ? arow : (rows - 1));
        aF = (const float*)Asrc + (size_t)pairtok[rr] * KSIZE + koff;
    } else {
        aH = (const __half*)Asrc + (size_t)(row0 + arow) * KSIZE + koff;
    }
    // ---- B staging: thread -> k-pair kr0=(tid>>4)*2, n base tid&15 ----
    int kr0 = (tid >> 4) * 2;
    int nbase = tid & 15;
    const float* bp0 = Ball + (size_t)e * KSIZE * LDB + (size_t)kr0 * LDB + n0 + nbase;

    float c[4][4][4];
    #pragma unroll
    for (int i = 0; i < 4; i++)
        #pragma unroll
        for (int j = 0; j < 4; j++)
            #pragma unroll
            for (int q = 0; q < 4; q++) c[i][j][q] = 0.f;

    uint32_t apre[8], bpre[8];

    auto prefetch = [&](int kb){
        if (GATHER){
            const float* ap = aF + kb*BK;
            #pragma unroll
            for (int j = 0; j < 4; j++){
                float4 v = *reinterpret_cast<const float4*>(ap + j*4);
                apre[2*j]   = pack_h2(v.x, v.y);
                apre[2*j+1] = pack_h2(v.z, v.w);
            }
        } else {
            const uint4* ap = reinterpret_cast<const uint4*>(aH + kb*BK);
            uint4 u0 = ap[0], u1 = ap[1];
            apre[0]=u0.x; apre[1]=u0.y; apre[2]=u0.z; apre[3]=u0.w;
            apre[4]=u1.x; apre[5]=u1.y; apre[6]=u1.z; apre[7]=u1.w;
        }
        const float* bp = bp0 + (size_t)kb*BK*LDB;
        #pragma unroll
        for (int j = 0; j < 8; j++){
            float f0 = bp[16*j];
            float f1 = bp[LDB + 16*j];
            bpre[j] = pack_h2(f0, f1);
        }
    };

    auto sts = [&](int buf){
        uint32_t* da = reinterpret_cast<uint32_t*>(As + buf*ASZ + arow*ASTR + koff);
        *reinterpret_cast<uint4*>(da)     = make_uint4(apre[0], apre[1], apre[2], apre[3]);
        *reinterpret_cast<uint4*>(da + 4) = make_uint4(apre[4], apre[5], apre[6], apre[7]);
        __half* bb = Bs + buf*BSZ;
        #pragma unroll
        for (int j = 0; j < 8; j++)
            *reinterpret_cast<uint32_t*>(bb + (nbase + 16*j)*BSTR + kr0) = bpre[j];
    };

    prefetch(0);
    sts(0);
    __syncthreads();

    const int NKB = KSIZE / BK;
    for (int kb = 0; kb < NKB; kb++){
        int cur = kb & 1;
        if (kb + 1 < NKB) prefetch(kb + 1);

        const __half* Ab = As + cur*ASZ;
        const __half* Bb = Bs + cur*BSZ;
        #pragma unroll
        for (int ks = 0; ks < 2; ks++){
            int kk = ks*16 + (lane & 3)*2;
            uint32_t afr[4][4], bfr[4][2];
            #pragma unroll
            for (int fm = 0; fm < 4; fm++){
                const __half* pa = Ab + (wm + fm*16 + (lane>>2))*ASTR + kk;
                afr[fm][0] = *reinterpret_cast<const uint32_t*>(pa);
                afr[fm][1] = *reinterpret_cast<const uint32_t*>(pa + 8*ASTR);
                afr[fm][2] = *reinterpret_cast<const uint32_t*>(pa + 8);
                afr[fm][3] = *reinterpret_cast<const uint32_t*>(pa + 8*ASTR + 8);
            }
            #pragma unroll
            for (int fn = 0; fn < 4; fn++){
                const __half* pb = Bb + (wn + fn*8 + (lane>>2))*BSTR + kk;
                bfr[fn][0] = *reinterpret_cast<const uint32_t*>(pb);
                bfr[fn][1] = *reinterpret_cast<const uint32_t*>(pb + 8);
            }
            #pragma unroll
            for (int fm = 0; fm < 4; fm++)
                #pragma unroll
                for (int fn = 0; fn < 4; fn++)
                    mma_fp16(c[fm][fn], afr[fm][0], afr[fm][1], afr[fm][2], afr[fm][3],
                             bfr[fn][0], bfr[fn][1]);
        }
        if (kb + 1 < NKB) sts(cur ^ 1);
        __syncthreads();
    }

    // ---- epilogue ----
    int r_lane = lane >> 2, c_lane = (lane & 3) * 2;
    #pragma unroll
    for (int fm = 0; fm < 4; fm++){
        #pragma unroll
        for (int half_i = 0; half_i < 2; half_i++){
            int mloc = wm + fm*16 + half_i*8 + r_lane;
            if (mloc < rows){
                const float* brw = bias + (size_t)e*LDB + n0;
                #pragma unroll
                for (int fn = 0; fn < 4; fn++){
                    int col = wn + fn*8 + c_lane;
                    float v0 = c[fm][fn][half_i*2+0] + brw[col];
                    float v1 = c[fm][fn][half_i*2+1] + brw[col+1];
                    if (GELU){
                        v0 = gelu_t(v0); v1 = gelu_t(v1);
                        __half* outp = (__half*)Cbuf + (size_t)(row0 + mloc)*LDB + n0 + col;
                        *reinterpret_cast<uint32_t*>(outp) = pack_h2(v0, v1);
                    } else {
                        float* outp = (float*)Cbuf + (size_t)(row0 + mloc)*LDB + n0 + col;
                        float2 st; st.x = v0; st.y = v1;
                        *reinterpret_cast<float2*>(outp) = st;
                    }
                }
            }
        }
    }
}

// ---------------- 5) weighted combine ----------------
__global__ void combine_kernel(float* __restrict__ out){
    int i = blockIdx.x, t = threadIdx.x;
    int s0 = g_slot[i*2], s1 = g_slot[i*2+1];
    float w0 = g_wn[i*2], w1 = g_wn[i*2+1];
    const float4* y0 = reinterpret_cast<const float4*>(g_Y + (size_t)s0*HDIM);
    const float4* y1 = reinterpret_cast<const float4*>(g_Y + (size_t)s1*HDIM);
    float4 a = y0[t], b = y1[t];
    float4 r;
    r.x = w0*a.x + w1*b.x; r.y = w0*a.y + w1*b.y;
    r.z = w0*a.z + w1*b.z; r.w = w0*a.w + w1*b.w;
    reinterpret_cast<float4*>(out + (size_t)i*HDIM)[t] = r;
}

// ---------------- launch ----------------
extern "C" void kernel_launch(void* const* d_in, const int* in_sizes, int n_in,
                              void* d_out, int out_size){
    const float* x       = (const float*)d_in[0];
    const int*   mapping = (const int*)  d_in[1];
    const float* Wg      = (const float*)d_in[2];
    const float* W1      = (const float*)d_in[3];
    const float* b1      = (const float*)d_in[4];
    const float* W2      = (const float*)d_in[5];
    const float* b2      = (const float*)d_in[6];
    float* out = (float*)d_out;

    float *pLog, *pSoft, *pY; __half* pHh; int *pTok;
    cudaGetSymbolAddress((void**)&pLog,  g_logits);
    cudaGetSymbolAddress((void**)&pSoft, g_soft);
    cudaGetSymbolAddress((void**)&pHh,   g_Hh);
    cudaGetSymbolAddress((void**)&pY,    g_Y);
    cudaGetSymbolAddress((void**)&pTok,  g_pairtok);

    gate_kernel<<<N_TOK, 256>>>(x, Wg, pLog);
    colsoftmax_kernel<<<NEXP, 256>>>(pLog, pSoft);
    assign_kernel<<<1, 512>>>(mapping, pSoft);

    int smem = 4*128*40 * (int)sizeof(__half);   // 40960 B
    moe_gemm_fp16<HDIM, FDIM, true,  true ><<<dim3(MAXTILES, FDIM/128), 256, smem>>>(x,   W1, b1, pHh, pTok);
    moe_gemm_fp16<FDIM, HDIM, false, false><<<dim3(MAXTILES, HDIM/128), 256, smem>>>(pHh, W2, b2, pY,  pTok);

    combine_kernel<<<N_TOK, 256>>>(out);
}

// round 5
// speedup vs baseline: 1.4886x; 1.0195x over previous
#include <cuda_runtime.h>
#include <cuda_fp16.h>
#include <math.h>
#include <cstdint>

#define N_TOK 2048
#define HDIM 1024
#define FDIM 4096
#define NEXP 8
#define KSEL 2
#define NPAIR (N_TOK*KSEL)
#define MAXTILES 40
#define BK 32

// ---------------- scratch (static device globals) ----------------
__device__ float  g_logits[N_TOK*NEXP];
__device__ float  g_soft[N_TOK*NEXP];
__device__ float  g_wn[NPAIR];
__device__ int    g_slot[NPAIR];
__device__ int    g_pairtok[NPAIR];
__device__ int    g_tiles[MAXTILES*3];
__device__ int    g_ntiles;
__device__ __half g_Hh[(size_t)(NPAIR+128)*FDIM];   // gelu(x@W1+b1) as fp16
__device__ float  g_Y[(size_t)(NPAIR+128)*HDIM];

// ---------------- helpers ----------------
__device__ __forceinline__ uint32_t pack_h2(float lo, float hi){
    uint32_t r;
    asm("cvt.rn.f16x2.f32 %0, %1, %2;" : "=r"(r) : "f"(hi), "f"(lo));
    return r;
}

__device__ __forceinline__ uint32_t smem_u32(const void* p){
    uint32_t a;
    asm("{ .reg .u64 t; cvta.to.shared.u64 t, %1; cvt.u32.u64 %0, t; }" : "=r"(a) : "l"(p));
    return a;
}

__device__ __forceinline__ void ldsm_x4(uint32_t& r0, uint32_t& r1, uint32_t& r2, uint32_t& r3,
                                        uint32_t addr){
    asm volatile("ldmatrix.sync.aligned.m8n8.x4.shared.b16 {%0,%1,%2,%3}, [%4];"
        : "=r"(r0), "=r"(r1), "=r"(r2), "=r"(r3) : "r"(addr));
}
__device__ __forceinline__ void ldsm_x4_t(uint32_t& r0, uint32_t& r1, uint32_t& r2, uint32_t& r3,
                                          uint32_t addr){
    asm volatile("ldmatrix.sync.aligned.m8n8.x4.trans.shared.b16 {%0,%1,%2,%3}, [%4];"
        : "=r"(r0), "=r"(r1), "=r"(r2), "=r"(r3) : "r"(addr));
}

__device__ __forceinline__ void mma_fp16(float c[4], uint32_t a0, uint32_t a1, uint32_t a2, uint32_t a3,
                                         uint32_t b0, uint32_t b1){
    asm volatile("mma.sync.aligned.m16n8k16.row.col.f32.f16.f16.f32 "
        "{%0,%1,%2,%3}, {%4,%5,%6,%7}, {%8,%9}, {%0,%1,%2,%3};\n"
        : "+f"(c[0]),"+f"(c[1]),"+f"(c[2]),"+f"(c[3])
        : "r"(a0),"r"(a1),"r"(a2),"r"(a3),"r"(b0),"r"(b1));
}

__device__ __forceinline__ float gelu_t(float v){
    float u = 0.7978845608028654f*(v + 0.044715f*v*v*v);
    return 0.5f*v*(1.f + tanhf(u));
}

// ---------------- 1) gating logits: x @ Wg^T ----------------
__global__ void gate_kernel(const float* __restrict__ x, const float* __restrict__ Wg,
                            float* __restrict__ logits){
    int i = blockIdx.x;
    int wid = threadIdx.x >> 5;
    int lane = threadIdx.x & 31;
    const float4* x4 = reinterpret_cast<const float4*>(x + (size_t)i*HDIM);
    const float4* w4 = reinterpret_cast<const float4*>(Wg + (size_t)wid*HDIM);
    float s = 0.f;
    #pragma unroll
    for (int k = lane; k < HDIM/4; k += 32){
        float4 a = x4[k], b = w4[k];
        s += a.x*b.x + a.y*b.y + a.z*b.z + a.w*b.w;
    }
    #pragma unroll
    for (int o = 16; o; o >>= 1) s += __shfl_xor_sync(0xffffffffu, s, o);
    if (lane == 0) logits[i*NEXP + wid] = s;
}

// ---------------- 2) softmax over axis=0 ----------------
__global__ void colsoftmax_kernel(const float* __restrict__ logits, float* __restrict__ soft){
    int e = blockIdx.x;
    int t = threadIdx.x;
    __shared__ float red[256];
    float m = -1e30f;
    for (int i = t; i < N_TOK; i += 256) m = fmaxf(m, logits[i*NEXP + e]);
    red[t] = m; __syncthreads();
    for (int o = 128; o; o >>= 1){ if (t < o) red[t] = fmaxf(red[t], red[t+o]); __syncthreads(); }
    float mx = red[0]; __syncthreads();
    float sum = 0.f;
    for (int i = t; i < N_TOK; i += 256) sum += expf(logits[i*NEXP + e] - mx);
    red[t] = sum; __syncthreads();
    for (int o = 128; o; o >>= 1){ if (t < o) red[t] += red[t+o]; __syncthreads(); }
    float inv = 1.f / red[0];
    for (int i = t; i < N_TOK; i += 256)
        soft[i*NEXP + e] = expf(logits[i*NEXP + e] - mx) * inv;
}

// ---------------- 3) deterministic assignment ----------------
__global__ void assign_kernel(const int* __restrict__ mapping, const float* __restrict__ soft){
    const int T = 512, PPT = NPAIR / T;
    int t = threadIdx.x;
    __shared__ int scan[T][NEXP];
    __shared__ int base[NEXP];

    int cnt[NEXP];
    #pragma unroll
    for (int e = 0; e < NEXP; e++) cnt[e] = 0;
    int le[PPT], lr[PPT];
    #pragma unroll
    for (int j = 0; j < PPT; j++){
        int p = t*PPT + j;
        int e = mapping[p];
        le[j] = e; lr[j] = cnt[e]; cnt[e]++;
    }
    #pragma unroll
    for (int e = 0; e < NEXP; e++) scan[t][e] = cnt[e];
    __syncthreads();
    for (int off = 1; off < T; off <<= 1){
        int v[NEXP];
        if (t >= off){
            #pragma unroll
            for (int e = 0; e < NEXP; e++) v[e] = scan[t-off][e];
        }
        __syncthreads();
        if (t >= off){
            #pragma unroll
            for (int e = 0; e < NEXP; e++) scan[t][e] += v[e];
        }
        __syncthreads();
    }
    if (t == 0){
        int acc = 0;
        for (int e = 0; e < NEXP; e++){ base[e] = acc; acc += scan[T-1][e]; }
        int nt = 0;
        for (int e = 0; e < NEXP; e++){
            int c = scan[T-1][e];
            for (int r = 0; r < c; r += 128){
                g_tiles[nt*3+0] = e;
                g_tiles[nt*3+1] = base[e] + r;
                g_tiles[nt*3+2] = min(128, c - r);
                nt++;
            }
        }
        g_ntiles = nt;
    }
    __syncthreads();
    int excl[NEXP];
    #pragma unroll
    for (int e = 0; e < NEXP; e++) excl[e] = (t > 0 ? scan[t-1][e] : 0);
    #pragma unroll
    for (int j = 0; j < PPT; j++){
        int p = t*PPT + j;
        int e = le[j];
        int dst = base[e] + excl[e] + lr[j];
        g_slot[p] = dst;
        g_pairtok[dst] = p >> 1;
    }
    #pragma unroll
    for (int ii = 0; ii < PPT/KSEL; ii++){
        int i = t*(PPT/KSEL) + ii;
        int e0 = mapping[i*KSEL], e1 = mapping[i*KSEL+1];
        float w0 = soft[i*NEXP + e0], w1 = soft[i*NEXP + e1];
        float inv = 1.f / (w0 + w1);
        g_wn[i*KSEL]   = w0*inv;
        g_wn[i*KSEL+1] = w1*inv;
    }
}

// ---------------- 4) fp16 grouped GEMM: 128x128 tile, BK=32, 8 warps, ldmatrix ----------------
// A smem: [2][128][40] half (M-major, K-contig). B smem: [2][32][136] half (K-major, N-contig).
#define ASTR 40
#define BSTR 136
#define ASZ (128*ASTR)
#define BSZ (BK*BSTR)

template<int KSIZE, int LDB, bool GELU, bool GATHER>
__global__ __launch_bounds__(256, 2) void moe_gemm_fp16(
    const void* __restrict__ Asrc,    // float x (GATHER) or half g_Hh
    const float* __restrict__ Ball,   // W [E][KSIZE][LDB] fp32
    const float* __restrict__ bias,   // [E][LDB]
    void* __restrict__ Cbuf,          // half (GELU) or float
    const int* __restrict__ pairtok)
{
    int tileIdx = blockIdx.x;
    if (tileIdx >= g_ntiles) return;
    int e    = g_tiles[tileIdx*3+0];
    int row0 = g_tiles[tileIdx*3+1];
    int rows = g_tiles[tileIdx*3+2];
    int n0   = blockIdx.y * 128;

    extern __shared__ __half smem[];
    __half* As = smem;               // [2][128][ASTR]
    __half* Bs = smem + 2*ASZ;       // [2][BK][BSTR]

    int tid = threadIdx.x;
    int wid = tid >> 5, lane = tid & 31;
    int wm = (wid >> 2) * 64, wn = (wid & 3) * 32;

    // ---- A staging: thread -> row tid>>1, half-offset (tid&1)*16 ----
    int arow = tid >> 1;
    int koff = (tid & 1) * 16;
    const float*  aF = nullptr;
    const __half* aH = nullptr;
    if (GATHER){
        int rr = row0 + ((arow < rows) ? arow : (rows - 1));
        aF = (const float*)Asrc + (size_t)pairtok[rr] * KSIZE + koff;
    } else {
        aH = (const __half*)Asrc + (size_t)(row0 + arow) * KSIZE + koff;
    }
    // ---- B staging: thread -> k-row tid>>3, n-offset (tid&7)*16 (16 n values, fp32->fp16) ----
    int bk = tid >> 3;
    int bnq = (tid & 7) * 16;
    const float* bp0 = Ball + (size_t)e * KSIZE * LDB + (size_t)bk * LDB + n0 + bnq;

    float c[4][4][4];
    #pragma unroll
    for (int i = 0; i < 4; i++)
        #pragma unroll
        for (int j = 0; j < 4; j++)
            #pragma unroll
            for (int q = 0; q < 4; q++) c[i][j][q] = 0.f;

    uint32_t apre[8], bpre[8];

    auto prefetch = [&](int kb){
        if (GATHER){
            const float* ap = aF + kb*BK;
            #pragma unroll
            for (int j = 0; j < 4; j++){
                float4 v = *reinterpret_cast<const float4*>(ap + j*4);
                apre[2*j]   = pack_h2(v.x, v.y);
                apre[2*j+1] = pack_h2(v.z, v.w);
            }
        } else {
            const uint4* ap = reinterpret_cast<const uint4*>(aH + kb*BK);
            uint4 u0 = ap[0], u1 = ap[1];
            apre[0]=u0.x; apre[1]=u0.y; apre[2]=u0.z; apre[3]=u0.w;
            apre[4]=u1.x; apre[5]=u1.y; apre[6]=u1.z; apre[7]=u1.w;
        }
        const float* bp = bp0 + (size_t)kb*BK*LDB;
        #pragma unroll
        for (int j = 0; j < 4; j++){
            float4 v = *reinterpret_cast<const float4*>(bp + j*4);
            bpre[2*j]   = pack_h2(v.x, v.y);
            bpre[2*j+1] = pack_h2(v.z, v.w);
        }
    };

    auto sts = [&](int buf){
        uint32_t* da = reinterpret_cast<uint32_t*>(As + buf*ASZ + arow*ASTR + koff);
        *reinterpret_cast<uint4*>(da)     = make_uint4(apre[0], apre[1], apre[2], apre[3]);
        *reinterpret_cast<uint4*>(da + 4) = make_uint4(apre[4], apre[5], apre[6], apre[7]);
        uint32_t* db = reinterpret_cast<uint32_t*>(Bs + buf*BSZ + bk*BSTR + bnq);
        *reinterpret_cast<uint4*>(db)     = make_uint4(bpre[0], bpre[1], bpre[2], bpre[3]);
        *reinterpret_cast<uint4*>(db + 4) = make_uint4(bpre[4], bpre[5], bpre[6], bpre[7]);
    };

    prefetch(0);
    sts(0);
    __syncthreads();

    // ---- per-lane ldmatrix address offsets (in halves) ----
    int a_row = ((lane>>3)&1)*8 + (lane&7);     // + row offset within 16-row fm tile
    int a_kof = ((lane>>4)&1)*8;                // k offset 0/8
    int b_kr  = ((lane>>3)&1)*8 + (lane&7);     // k row within 16-k chunk
    int b_nof = ((lane>>4)&1)*8;                // n offset 0/8 (fn pair)

    uint32_t sbA = smem_u32(As);
    uint32_t sbB = smem_u32(Bs);
    uint32_t aoff = (uint32_t)((wm + a_row)*ASTR + a_kof) * 2u;
    uint32_t boff = (uint32_t)(b_kr*BSTR + wn + b_nof) * 2u;

    const int NKB = KSIZE / BK;
    for (int kb = 0; kb < NKB; kb++){
        int cur = kb & 1;
        if (kb + 1 < NKB) prefetch(kb + 1);

        uint32_t abase = sbA + (uint32_t)cur*(ASZ*2) + aoff;
        uint32_t bbase = sbB + (uint32_t)cur*(BSZ*2) + boff;
        #pragma unroll
        for (int ks = 0; ks < 2; ks++){
            uint32_t afr[4][4], bfr[4][2];
            #pragma unroll
            for (int fm = 0; fm < 4; fm++)
                ldsm_x4(afr[fm][0], afr[fm][1], afr[fm][2], afr[fm][3],
                        abase + (uint32_t)(fm*16*ASTR*2) + (uint32_t)(ks*32));
            #pragma unroll
            for (int fn2 = 0; fn2 < 2; fn2++)
                ldsm_x4_t(bfr[2*fn2][0], bfr[2*fn2][1], bfr[2*fn2+1][0], bfr[2*fn2+1][1],
                          bbase + (uint32_t)(ks*16*BSTR*2) + (uint32_t)(fn2*32));
            #pragma unroll
            for (int fm = 0; fm < 4; fm++)
                #pragma unroll
                for (int fn = 0; fn < 4; fn++)
                    mma_fp16(c[fm][fn], afr[fm][0], afr[fm][1], afr[fm][2], afr[fm][3],
                             bfr[fn][0], bfr[fn][1]);
        }
        if (kb + 1 < NKB) sts(cur ^ 1);
        __syncthreads();
    }

    // ---- epilogue ----
    int r_lane = lane >> 2, c_lane = (lane & 3) * 2;
    #pragma unroll
    for (int fm = 0; fm < 4; fm++){
        #pragma unroll
        for (int half_i = 0; half_i < 2; half_i++){
            int mloc = wm + fm*16 + half_i*8 + r_lane;
            if (mloc < rows){
                const float* brw = bias + (size_t)e*LDB + n0;
                #pragma unroll
                for (int fn = 0; fn < 4; fn++){
                    int col = wn + fn*8 + c_lane;
                    float v0 = c[fm][fn][half_i*2+0] + brw[col];
                    float v1 = c[fm][fn][half_i*2+1] + brw[col+1];
                    if (GELU){
                        v0 = gelu_t(v0); v1 = gelu_t(v1);
                        __half* outp = (__half*)Cbuf + (size_t)(row0 + mloc)*LDB + n0 + col;
                        *reinterpret_cast<uint32_t*>(outp) = pack_h2(v0, v1);
                    } else {
                        float* outp = (float*)Cbuf + (size_t)(row0 + mloc)*LDB + n0 + col;
                        float2 st; st.x = v0; st.y = v1;
                        *reinterpret_cast<float2*>(outp) = st;
                    }
                }
            }
        }
    }
}

// ---------------- 5) weighted combine ----------------
__global__ void combine_kernel(float* __restrict__ out){
    int i = blockIdx.x, t = threadIdx.x;
    int s0 = g_slot[i*2], s1 = g_slot[i*2+1];
    float w0 = g_wn[i*2], w1 = g_wn[i*2+1];
    const float4* y0 = reinterpret_cast<const float4*>(g_Y + (size_t)s0*HDIM);
    const float4* y1 = reinterpret_cast<const float4*>(g_Y + (size_t)s1*HDIM);
    float4 a = y0[t], b = y1[t];
    float4 r;
    r.x = w0*a.x + w1*b.x; r.y = w0*a.y + w1*b.y;
    r.z = w0*a.z + w1*b.z; r.w = w0*a.w + w1*b.w;
    reinterpret_cast<float4*>(out + (size_t)i*HDIM)[t] = r;
}

// ---------------- launch ----------------
extern "C" void kernel_launch(void* const* d_in, const int* in_sizes, int n_in,
                              void* d_out, int out_size){
    const float* x       = (const float*)d_in[0];
    const int*   mapping = (const int*)  d_in[1];
    const float* Wg      = (const float*)d_in[2];
    const float* W1      = (const float*)d_in[3];
    const float* b1      = (const float*)d_in[4];
    const float* W2      = (const float*)d_in[5];
    const float* b2      = (const float*)d_in[6];
    float* out = (float*)d_out;

    float *pLog, *pSoft, *pY; __half* pHh; int *pTok;
    cudaGetSymbolAddress((void**)&pLog,  g_logits);
    cudaGetSymbolAddress((void**)&pSoft, g_soft);
    cudaGetSymbolAddress((void**)&pHh,   g_Hh);
    cudaGetSymbolAddress((void**)&pY,    g_Y);
    cudaGetSymbolAddress((void**)&pTok,  g_pairtok);

    gate_kernel<<<N_TOK, 256>>>(x, Wg, pLog);
    colsoftmax_kernel<<<NEXP, 256>>>(pLog, pSoft);
    assign_kernel<<<1, 512>>>(mapping, pSoft);

    int smem = (2*ASZ + 2*BSZ) * (int)sizeof(__half);   // 37888 B
    moe_gemm_fp16<HDIM, FDIM, true,  true ><<<dim3(MAXTILES, FDIM/128), 256, smem>>>(x,   W1, b1, pHh, pTok);
    moe_gemm_fp16<FDIM, HDIM, false, false><<<dim3(MAXTILES, HDIM/128), 256, smem>>>(pHh, W2, b2, pY,  pTok);

    combine_kernel<<<N_TOK, 256>>>(out);
}